// round 1
// baseline (speedup 1.0000x reference)
#include <cuda_runtime.h>
#include <cstdint>

// Problem constants (fixed by the dataset)
#define S_LEN 16384
#define D_DIM 256
#define V_DIM 8
#define K_HEADS 24

__device__ __forceinline__ unsigned long long packf2(float lo, float hi) {
    unsigned long long r;
    asm("mov.b64 %0, {%1, %2};" : "=l"(r) : "f"(lo), "f"(hi));
    return r;
}
__device__ __forceinline__ void unpackf2(unsigned long long p, float& lo, float& hi) {
    asm("mov.b64 {%0, %1}, %2;" : "=f"(lo), "=f"(hi) : "l"(p));
}
// d = a*b + d on packed f32x2 (2x fp32 FMA throughput on sm_100+)
__device__ __forceinline__ void fmaf2(unsigned long long& d, unsigned long long a,
                                      unsigned long long b) {
    asm("fma.rn.f32x2 %0, %1, %2, %0;" : "+l"(d) : "l"(a), "l"(b));
}

__global__ __launch_bounds__(256, 2)
void attr_decoder_kernel(const float* __restrict__ feats,      // [N, 256]
                         const int*   __restrict__ mask_idx,   // [24, 16384]
                         const float* __restrict__ Wh,         // [24, 256, 8]
                         const float* __restrict__ bias,       // [24, 8]
                         float*       __restrict__ out)        // [24, 16384, 8]
{
    const int k    = blockIdx.y;
    const int lane = threadIdx.x & 31;
    const int warp = threadIdx.x >> 5;
    const int s0   = blockIdx.x * 256 + warp * 32;   // 32 rows per warp

    // ---- Load this head's weights into registers, packed as f32x2 pairs.
    // Lane owns d-slice d = lane*8 + i, i in [0,8). wp[i][p] = (W[d][2p], W[d][2p+1])
    unsigned long long wp[8][4];
    const float4* wk = (const float4*)(Wh + (size_t)k * (D_DIM * V_DIM));
    #pragma unroll
    for (int i = 0; i < 8; ++i) {
        int d = lane * 8 + i;
        float4 A = wk[d * 2 + 0];
        float4 B = wk[d * 2 + 1];
        wp[i][0] = packf2(A.x, A.y);
        wp[i][1] = packf2(A.z, A.w);
        wp[i][2] = packf2(B.x, B.y);
        wp[i][3] = packf2(B.z, B.w);
    }
    const float bias_v = bias[k * V_DIM + (lane & 7)];

    // One gather index per lane covers the warp's 32 rows.
    const int idxv = mask_idx[(size_t)k * S_LEN + s0 + lane];

    // Prefetch row 0
    {
        // nothing
    }
    int i0 = __shfl_sync(0xffffffffu, idxv, 0);
    const float4* fr0 = (const float4*)(feats + (size_t)i0 * D_DIM) + lane * 2;
    float4 fa = fr0[0];
    float4 fb = fr0[1];

    float keepval = 0.0f;

    #pragma unroll 4
    for (int r = 0; r < 32; ++r) {
        const float4 ca = fa, cb = fb;
        // Software prefetch next row (hides L2/DRAM gather latency)
        if (r + 1 < 32) {
            int ni = __shfl_sync(0xffffffffu, idxv, r + 1);
            const float4* nf = (const float4*)(feats + (size_t)ni * D_DIM) + lane * 2;
            fa = nf[0];
            fb = nf[1];
        }

        // ---- Packed FMA accumulation: acc[p] holds (v=2p, v=2p+1)
        const float f[8] = {ca.x, ca.y, ca.z, ca.w, cb.x, cb.y, cb.z, cb.w};
        unsigned long long acc[4] = {0ull, 0ull, 0ull, 0ull};
        #pragma unroll
        for (int i = 0; i < 8; ++i) {
            unsigned long long fd = packf2(f[i], f[i]);
            #pragma unroll
            for (int p = 0; p < 4; ++p) fmaf2(acc[p], fd, wp[i][p]);
        }
        float a[8];
        #pragma unroll
        for (int p = 0; p < 4; ++p) unpackf2(acc[p], a[2 * p], a[2 * p + 1]);

        // ---- Reduce-scatter across 32 lanes: lane l ends with v = l&7.
        #pragma unroll
        for (int v = 0; v < 8; ++v) a[v] += __shfl_xor_sync(0xffffffffu, a[v], 16);
        #pragma unroll
        for (int v = 0; v < 8; ++v) a[v] += __shfl_xor_sync(0xffffffffu, a[v], 8);

        const bool hi2 = (lane & 4) != 0;
        float t[4];
        #pragma unroll
        for (int j = 0; j < 4; ++j) {
            float keep = hi2 ? a[4 + j] : a[j];
            float send = hi2 ? a[j]     : a[4 + j];
            t[j] = keep + __shfl_xor_sync(0xffffffffu, send, 4);
        }
        const bool hi1 = (lane & 2) != 0;
        float u[2];
        #pragma unroll
        for (int j = 0; j < 2; ++j) {
            float keep = hi1 ? t[2 + j] : t[j];
            float send = hi1 ? t[j]     : t[2 + j];
            u[j] = keep + __shfl_xor_sync(0xffffffffu, send, 2);
        }
        const bool hi0 = (lane & 1) != 0;
        float keep = hi0 ? u[1] : u[0];
        float send = hi0 ? u[0] : u[1];
        float res  = keep + __shfl_xor_sync(0xffffffffu, send, 1) + bias_v;

        // Buffer 4 rows, then one coalesced 128B warp store.
        if ((lane >> 3) == (r & 3)) keepval = res;
        if ((r & 3) == 3) {
            out[((size_t)k * S_LEN + s0 + (r - 3)) * V_DIM + lane] = keepval;
        }
    }
}

extern "C" void kernel_launch(void* const* d_in, const int* in_sizes, int n_in,
                              void* d_out, int out_size) {
    // metadata order: block_type_grid (unused), features, mask_idx, head_weights, head_bias
    const float* feats    = (const float*)d_in[1];
    const int*   mask_idx = (const int*)  d_in[2];
    const float* Wh       = (const float*)d_in[3];
    const float* bias     = (const float*)d_in[4];
    float*       out      = (float*)d_out;

    dim3 grid(S_LEN / 256, K_HEADS);   // 64 x 24 blocks, 8 warps each, 32 rows/warp
    attr_decoder_kernel<<<grid, 256>>>(feats, mask_idx, Wh, bias, out);
}

// round 2
// speedup vs baseline: 1.1736x; 1.1736x over previous
#include <cuda_runtime.h>
#include <cstdint>

#define S_LEN 16384
#define D_DIM 256
#define V_DIM 8
#define K_HEADS 24

__device__ __forceinline__ unsigned long long packf2(float lo, float hi) {
    unsigned long long r;
    asm("mov.b64 %0, {%1, %2};" : "=l"(r) : "f"(lo), "f"(hi));
    return r;
}
__device__ __forceinline__ void unpackf2(unsigned long long p, float& lo, float& hi) {
    asm("mov.b64 {%0, %1}, %2;" : "=f"(lo), "=f"(hi) : "l"(p));
}
// d = a*b + d on packed f32x2 (2x fp32 FMA throughput on sm_100+)
__device__ __forceinline__ void fmaf2(unsigned long long& d, unsigned long long a,
                                      unsigned long long b) {
    asm("fma.rn.f32x2 %0, %1, %2, %0;" : "+l"(d) : "l"(a), "l"(b));
}

__global__ __launch_bounds__(256, 2)
void attr_decoder_kernel(const float* __restrict__ feats,      // [N, 256]
                         const int*   __restrict__ mask_idx,   // [24, 16384]
                         const float* __restrict__ Wh,         // [24, 256, 8]
                         const float* __restrict__ bias,       // [24, 8]
                         float*       __restrict__ out)        // [24, 16384, 8]
{
    const int k    = blockIdx.y;
    const int lane = threadIdx.x & 31;
    const int warp = threadIdx.x >> 5;
    const int s0   = blockIdx.x * 256 + warp * 32;   // 32 rows per warp

    // ---- Per-head weights in registers, packed f32x2 by v-pair.
    // Lane owns d = lane*8 + i, i in [0,8). wp[i][p] = (W[d][2p], W[d][2p+1])
    unsigned long long wp[8][4];
    const float4* wk = (const float4*)(Wh + (size_t)k * (D_DIM * V_DIM));
    #pragma unroll
    for (int i = 0; i < 8; ++i) {
        int d = lane * 8 + i;
        float4 A = wk[d * 2 + 0];
        float4 B = wk[d * 2 + 1];
        wp[i][0] = packf2(A.x, A.y);
        wp[i][1] = packf2(A.z, A.w);
        wp[i][2] = packf2(B.x, B.y);
        wp[i][3] = packf2(B.z, B.w);
    }
    // After fold-first reduce-scatter, lane l holds v = (l>>2)&7.
    const int  vown   = (lane >> 2) & 7;
    const float bias_v = bias[k * V_DIM + vown];

    // One gather index per lane covers the warp's 32 rows.
    const int idxv = mask_idx[(size_t)k * S_LEN + s0 + lane];

    // Prefetch row 0
    int i0 = __shfl_sync(0xffffffffu, idxv, 0);
    const float4* fr0 = (const float4*)(feats + (size_t)i0 * D_DIM) + lane * 2;
    float4 fa = fr0[0];
    float4 fb = fr0[1];

    const bool b4 = (lane & 16) != 0;
    const bool b3 = (lane & 8)  != 0;
    const bool b2 = (lane & 4)  != 0;

    float keepval = 0.0f;

    #pragma unroll 4
    for (int r = 0; r < 32; ++r) {
        const float4 ca = fa, cb = fb;
        // Software prefetch next row (hides L2/DRAM gather latency)
        if (r + 1 < 32) {
            int ni = __shfl_sync(0xffffffffu, idxv, r + 1);
            const float4* nf = (const float4*)(feats + (size_t)ni * D_DIM) + lane * 2;
            fa = nf[0];
            fb = nf[1];
        }

        // ---- Packed FMA: acc[p] holds partial (v=2p, v=2p+1) over this lane's 8 d's.
        const float f[8] = {ca.x, ca.y, ca.z, ca.w, cb.x, cb.y, cb.z, cb.w};
        unsigned long long acc[4] = {0ull, 0ull, 0ull, 0ull};
        #pragma unroll
        for (int i = 0; i < 8; ++i) {
            unsigned long long fd = packf2(f[i], f[i]);
            #pragma unroll
            for (int p = 0; p < 4; ++p) fmaf2(acc[p], fd, wp[i][p]);
        }
        float a[8];
        #pragma unroll
        for (int p = 0; p < 4; ++p) unpackf2(acc[p], a[2 * p], a[2 * p + 1]);

        // ---- Fold-first reduce-scatter: 9 shfl total.
        // Stage off16: fold 8 -> 4 (v bit2 chosen by lane bit4)
        float t[4];
        #pragma unroll
        for (int j = 0; j < 4; ++j) {
            float keep = b4 ? a[4 + j] : a[j];
            float send = b4 ? a[j]     : a[4 + j];
            t[j] = keep + __shfl_xor_sync(0xffffffffu, send, 16);
        }
        // Stage off8: fold 4 -> 2 (v bit1 chosen by lane bit3)
        float u[2];
        #pragma unroll
        for (int j = 0; j < 2; ++j) {
            float keep = b3 ? t[2 + j] : t[j];
            float send = b3 ? t[j]     : t[2 + j];
            u[j] = keep + __shfl_xor_sync(0xffffffffu, send, 8);
        }
        // Stage off4: fold 2 -> 1 (v bit0 chosen by lane bit2)
        float keep = b2 ? u[1] : u[0];
        float send = b2 ? u[0] : u[1];
        float w = keep + __shfl_xor_sync(0xffffffffu, send, 4);
        // Remaining sum over lane bits 1,0: plain butterflies
        w += __shfl_xor_sync(0xffffffffu, w, 2);
        w += __shfl_xor_sync(0xffffffffu, w, 1);
        const float res = w + bias_v;   // lane l holds v=(l>>2)&7, replica across l&3

        // Buffer 4 rows (replica (lane&3) keeps row rbase+(lane&3)),
        // then one coalesced, lane-permuted 128B warp store.
        if ((lane & 3) == (r & 3)) keepval = res;
        if ((r & 3) == 3) {
            out[((size_t)k * S_LEN + s0 + (r - 3) + (lane & 3)) * V_DIM + vown] = keepval;
        }
    }
}

extern "C" void kernel_launch(void* const* d_in, const int* in_sizes, int n_in,
                              void* d_out, int out_size) {
    // metadata order: block_type_grid (unused), features, mask_idx, head_weights, head_bias
    const float* feats    = (const float*)d_in[1];
    const int*   mask_idx = (const int*)  d_in[2];
    const float* Wh       = (const float*)d_in[3];
    const float* bias     = (const float*)d_in[4];
    float*       out      = (float*)d_out;

    dim3 grid(S_LEN / 256, K_HEADS);   // 64 x 24 blocks, 8 warps each, 32 rows/warp
    attr_decoder_kernel<<<grid, 256>>>(feats, mask_idx, Wh, bias, out);
}